// round 4
// baseline (speedup 1.0000x reference)
#include <cuda_runtime.h>

// OBMC, smem-tiled: stage a zero-padded per-channel row window in shared
// memory with coalesced float4 loads; serve all 12 bilinear taps (5 fused
// output groups per flow pixel, cf. R2 derivation) from LDS.
//
// Zero-padding (zero row + zero col pads) replaces validity masking: invalid
// taps read stored zeros, so inner loop weights are the unmasked bilinear
// weights. Pixels whose valid taps fall outside the staged window (|fy|>12,
// ~0.27%) take the exact global-gather fallback path.

#define BB 4
#define CC 64
#define HH 256
#define WW 256
#define HW (HH * WW)

#define TILE_H 4
#define FMAX 12
#define WROWS 32               // 2*FMAX + 8
#define WSTRIDE 264            // 4 zero cols | 256 data | 4 zero cols
#define ZROW 32                // dedicated all-zero row
#define WSIZE ((WROWS + 1) * WSTRIDE)
#define CPB 32                 // channels per block
#define NCG (CC / CPB)

__global__ __launch_bounds__(256, 2)
void obmc_tiled(const float* __restrict__ x,
                const float* __restrict__ flow,
                float* __restrict__ out)
{
    __shared__ float win[2][WSIZE];

    const int tid = threadIdx.x;                 // output col
    const int Y0  = blockIdx.x * TILE_H;
    const int b   = blockIdx.y;
    const int c0  = blockIdx.z * CPB;
    const int winLo = Y0 - (FMAX + 2);

    // ---- one-time pads: zero row + zero col pads in both buffers ----
    for (int i = tid; i < WSTRIDE; i += 256) {
        win[0][ZROW * WSTRIDE + i] = 0.f;
        win[1][ZROW * WSTRIDE + i] = 0.f;
    }
    for (int i = tid; i < WROWS * 8; i += 256) {
        const int r = i >> 3, k = i & 7;
        const int col = (k < 4) ? k : (256 + k);  // 0..3 and 260..263
        win[0][r * WSTRIDE + col] = 0.f;
        win[1][r * WSTRIDE + col] = 0.f;
    }

    // ---- per-pixel params (channel-invariant), kept in registers ----
    float w00[TILE_H], w01[TILE_H], w10[TILE_H], w11[TILE_H];
    unsigned po[TILE_H][6];     // 12 uint16 smem offsets, packed
    unsigned offC[TILE_H];      // center value offset (border copies)
    unsigned fbmask = 0;

    const float* fl = flow + (size_t)b * 2 * HW;
    #pragma unroll
    for (int t = 0; t < TILE_H; ++t) {
        const int Yo = Y0 + t;
        const int pix = Yo * WW + tid;
        const float fx = fl[pix];
        const float fy = fl[HW + pix];
        const float gx = (float)tid + fx;
        const float gy = (float)Yo  + fy;
        const float x0f = floorf(gx), y0f = floorf(gy);
        const float wx = gx - x0f,    wy = gy - y0f;
        const int x0 = (int)x0f, y0 = (int)y0f;
        w00[t] = (1.f - wx) * (1.f - wy);
        w01[t] = wx * (1.f - wy);
        w10[t] = (1.f - wx) * wy;
        w11[t] = wx * wy;

        int srow[4];
        bool fb = false;
        #pragma unroll
        for (int i = 0; i < 4; ++i) {
            const int r = y0 - 1 + i;
            if (r >= 0 && r < HH) {
                const int s = r - winLo;
                if (s < 0 || s >= WROWS) fb = true;
                srow[i] = min(max(s, 0), WROWS - 1);
            } else {
                srow[i] = ZROW;                  // reads zero
            }
        }
        int scol[4];
        #pragma unroll
        for (int j = 0; j < 4; ++j)
            scol[j] = min(max(x0 - 1 + j + 4, 0), WSTRIDE - 1);  // pads are zero

        #define OFS(i, j) ((unsigned)(srow[i] * WSTRIDE + scol[j]))
        po[t][0] = OFS(1,0) | (OFS(1,1) << 16);
        po[t][1] = OFS(1,2) | (OFS(1,3) << 16);
        po[t][2] = OFS(2,0) | (OFS(2,1) << 16);
        po[t][3] = OFS(2,2) | (OFS(2,3) << 16);
        po[t][4] = OFS(0,1) | (OFS(0,2) << 16);
        po[t][5] = OFS(3,1) | (OFS(3,2) << 16);
        #undef OFS
        offC[t] = (unsigned)((Yo - winLo) * WSTRIDE + tid + 4);
        if (fb) fbmask |= 1u << t;
    }

    const float* xg = x + ((size_t)b * CC + c0) * HW;

    // ---- stage channel 0 into buffer 0 ----
    #pragma unroll
    for (int k = 0; k < 8; ++k) {
        const int idx = tid + k * 256;           // WROWS*64 = 2048 float4s
        const int row = idx >> 6, c4 = (idx & 63) << 2;
        const int sr = winLo + row;
        float4 v = make_float4(0.f, 0.f, 0.f, 0.f);
        if (sr >= 0 && sr < HH) v = *(const float4*)(xg + (size_t)sr * WW + c4);
        *(float4*)&win[0][row * WSTRIDE + 4 + c4] = v;
    }
    __syncthreads();

    int cur = 0;
    for (int c = 0; c < CPB; ++c) {
        // prefetch next channel's window into registers (latency overlaps compute)
        float4 st[8];
        const bool more = (c + 1 < CPB);
        if (more) {
            const float* plane = xg + (size_t)(c + 1) * HW;
            #pragma unroll
            for (int k = 0; k < 8; ++k) {
                const int idx = tid + k * 256;
                const int row = idx >> 6, c4 = (idx & 63) << 2;
                const int sr = winLo + row;
                st[k] = make_float4(0.f, 0.f, 0.f, 0.f);
                if (sr >= 0 && sr < HH)
                    st[k] = *(const float4*)(plane + (size_t)sr * WW + c4);
            }
        }

        // ---- compute channel c from win[cur] ----
        const float* __restrict__ buf = win[cur];
        const int cch = c0 + c;
        #pragma unroll
        for (int t = 0; t < TILE_H; ++t) {
            const int Yo = Y0 + t;
            const int pix = Yo * WW + tid;
            float v0, v1, v2, v3, v4;

            if (fbmask & (1u << t)) {
                // rare exact global fallback (R2 path)
                const float fx = fl[pix], fy = fl[HW + pix];
                const float gx = (float)tid + fx, gy = (float)Yo + fy;
                const float x0f = floorf(gx), y0f = floorf(gy);
                const float wx = gx - x0f, wy = gy - y0f;
                const int x0 = (int)x0f, y0 = (int)y0f;
                int rofs[4], cofs[4]; float vr[4], vc[4];
                #pragma unroll
                for (int i = 0; i < 4; ++i) {
                    const int r = y0 - 1 + i;
                    vr[i] = (r >= 0 && r < HH) ? 1.f : 0.f;
                    rofs[i] = min(max(r, 0), HH - 1) * WW;
                    const int cI = x0 - 1 + i;
                    vc[i] = (cI >= 0 && cI < WW) ? 1.f : 0.f;
                    cofs[i] = min(max(cI, 0), WW - 1);
                }
                const float b00 = (1.f-wx)*(1.f-wy), b01 = wx*(1.f-wy);
                const float b10 = (1.f-wx)*wy,       b11 = wx*wy;
                const float* p = x + ((size_t)b * CC + cch) * HW;
                const float t10 = __ldg(p + rofs[1] + cofs[0]) * vr[1] * vc[0];
                const float t11 = __ldg(p + rofs[1] + cofs[1]) * vr[1] * vc[1];
                const float t12 = __ldg(p + rofs[1] + cofs[2]) * vr[1] * vc[2];
                const float t13 = __ldg(p + rofs[1] + cofs[3]) * vr[1] * vc[3];
                const float t20 = __ldg(p + rofs[2] + cofs[0]) * vr[2] * vc[0];
                const float t21 = __ldg(p + rofs[2] + cofs[1]) * vr[2] * vc[1];
                const float t22 = __ldg(p + rofs[2] + cofs[2]) * vr[2] * vc[2];
                const float t23 = __ldg(p + rofs[2] + cofs[3]) * vr[2] * vc[3];
                const float t01 = __ldg(p + rofs[0] + cofs[1]) * vr[0] * vc[1];
                const float t02 = __ldg(p + rofs[0] + cofs[2]) * vr[0] * vc[2];
                const float t31 = __ldg(p + rofs[3] + cofs[1]) * vr[3] * vc[1];
                const float t32 = __ldg(p + rofs[3] + cofs[2]) * vr[3] * vc[2];
                v0 = fmaf(b11,t22, fmaf(b10,t21, fmaf(b01,t12, b00*t11)));
                v1 = fmaf(b11,t12, fmaf(b10,t11, fmaf(b01,t02, b00*t01)));
                v3 = fmaf(b11,t32, fmaf(b10,t31, fmaf(b01,t22, b00*t21)));
                v2 = fmaf(b11,t21, fmaf(b10,t20, fmaf(b01,t11, b00*t10)));
                v4 = fmaf(b11,t23, fmaf(b10,t22, fmaf(b01,t13, b00*t12)));
            } else {
                const float t10 = buf[po[t][0] & 0xFFFFu];
                const float t11 = buf[po[t][0] >> 16];
                const float t12 = buf[po[t][1] & 0xFFFFu];
                const float t13 = buf[po[t][1] >> 16];
                const float t20 = buf[po[t][2] & 0xFFFFu];
                const float t21 = buf[po[t][2] >> 16];
                const float t22 = buf[po[t][3] & 0xFFFFu];
                const float t23 = buf[po[t][3] >> 16];
                const float t01 = buf[po[t][4] & 0xFFFFu];
                const float t02 = buf[po[t][4] >> 16];
                const float t31 = buf[po[t][5] & 0xFFFFu];
                const float t32 = buf[po[t][5] >> 16];
                v0 = fmaf(w11[t],t22, fmaf(w10[t],t21, fmaf(w01[t],t12, w00[t]*t11)));
                v1 = fmaf(w11[t],t12, fmaf(w10[t],t11, fmaf(w01[t],t02, w00[t]*t01)));
                v3 = fmaf(w11[t],t32, fmaf(w10[t],t31, fmaf(w01[t],t22, w00[t]*t21)));
                v2 = fmaf(w11[t],t21, fmaf(w10[t],t20, fmaf(w01[t],t11, w00[t]*t10)));
                v4 = fmaf(w11[t],t23, fmaf(w10[t],t22, fmaf(w01[t],t13, w00[t]*t12)));
            }

            const size_t gbase = ((size_t)(b * 5) * CC + cch) * HW + (size_t)pix;
            __stcs(out + gbase, v0);                                        // g0 @ (Yo, xp)
            if (Yo  >= 1)      __stcs(out + gbase + (size_t)1*CC*HW - WW, v1);
            if (tid >= 1)      __stcs(out + gbase + (size_t)2*CC*HW - 1,  v2);
            if (Yo  <= HH - 2) __stcs(out + gbase + (size_t)3*CC*HW + WW, v3);
            if (tid <= WW - 2) __stcs(out + gbase + (size_t)4*CC*HW + 1,  v4);

            if ((Yo == HH - 1) | (Yo == 0) | (tid == WW - 1) | (tid == 0)) {
                const float xv = buf[offC[t]];    // identity copy (zero shifted flow)
                if (Yo == HH - 1)  __stcs(out + gbase + (size_t)1*CC*HW, xv);
                if (Yo == 0)       __stcs(out + gbase + (size_t)3*CC*HW, xv);
                if (tid == WW - 1) __stcs(out + gbase + (size_t)2*CC*HW, xv);
                if (tid == 0)      __stcs(out + gbase + (size_t)4*CC*HW, xv);
            }
        }

        if (more) {
            float* nb = win[cur ^ 1];
            #pragma unroll
            for (int k = 0; k < 8; ++k) {
                const int idx = tid + k * 256;
                const int row = idx >> 6, c4 = (idx & 63) << 2;
                *(float4*)&nb[row * WSTRIDE + 4 + c4] = st[k];
            }
        }
        __syncthreads();
        cur ^= 1;
    }
}

extern "C" void kernel_launch(void* const* d_in, const int* in_sizes, int n_in,
                              void* d_out, int out_size) {
    const float* x    = (const float*)d_in[0];
    const float* flow = (const float*)d_in[1];
    float* out        = (float*)d_out;

    dim3 grid(HH / TILE_H, BB, NCG);   // 64 x 4 x 2 = 512 blocks
    dim3 block(256);
    obmc_tiled<<<grid, block>>>(x, flow, out);
}

// round 5
// speedup vs baseline: 1.4013x; 1.4013x over previous
#include <cuda_runtime.h>

// OBMC two-pass, channels-last gather.
// Pass 1: transpose x[B,C,H,W] -> xT[B,HW,C] (channels contiguous).
// Pass 2: per output pixel, 5 groups x 4 bilinear taps; each tap reads 64
//         contiguous channel floats from xT. Warp = 2 pixels x 16 lanes
//         (float4 of 4 channels per lane) -> gathers are 256B-segment loads
//         instead of 32 scattered scalars. Results staged in smem, stored
//         coalesced in channel-major out[B,5C,H,W].
//
// Group g's shifted flow: src=(Y+sy, X+sx); OOB src -> zero flow -> bilinear
// collapses to exact identity copy (matches reference semantics exactly).

#define BB 4
#define CC 64
#define HH 256
#define WW 256
#define HW (HH * WW)

__device__ float g_xT[(size_t)BB * HW * CC];   // 67 MB scratch

// ---------------- Pass 1: transpose to channels-last ----------------
__global__ __launch_bounds__(256)
void obmc_transpose(const float* __restrict__ x) {
    __shared__ float t[32][33];
    const int b  = blockIdx.z;
    const int cb = blockIdx.y * 32;
    const int pb = blockIdx.x * 32;
    const int tx = threadIdx.x;        // 0..31
    const int ty = threadIdx.y;        // 0..7

    const float* xb = x + ((size_t)b * CC + cb) * HW + pb;
    #pragma unroll
    for (int i = 0; i < 32; i += 8)
        t[ty + i][tx] = xb[(size_t)(ty + i) * HW + tx];
    __syncthreads();

    float* o = g_xT + ((size_t)b * HW + pb) * CC + cb;
    #pragma unroll
    for (int i = 0; i < 32; i += 8)
        o[(size_t)(ty + i) * CC + tx] = t[tx][ty + i];
}

// ---------------- Pass 2: gather + store ----------------
#define PXT 16   // pixels per block

__global__ __launch_bounds__(256, 3)
void obmc_gather(const float* __restrict__ flow, float* __restrict__ out) {
    __shared__ float st[5][PXT][65];

    const int tid = threadIdx.x;
    const int l   = tid & 31;
    const int w   = tid >> 5;                 // warp 0..7
    const int pxl = (w << 1) | (l >> 4);      // local pixel 0..15
    const int ch4 = l & 15;                   // float4 slice 0..15
    const int X0  = blockIdx.x * PXT;
    const int Y   = blockIdx.y;
    const int b   = blockIdx.z;
    const int xp  = X0 + pxl;

    const float* fb  = flow + (size_t)b * 2 * HW;
    const float* xTb = g_xT + (size_t)b * HW * CC;

    const int sxA[5] = {0, 0, 1,  0, -1};
    const int syA[5] = {0, 1, 0, -1,  0};

    #pragma unroll
    for (int g = 0; g < 5; ++g) {
        // shifted flow source (OOB -> zero flow -> exact identity sample)
        const int xs = xp + sxA[g];
        const int ys = Y  + syA[g];
        float fx = 0.f, fy = 0.f;
        if ((unsigned)xs < WW && (unsigned)ys < HH) {
            const int sp = ys * WW + xs;
            fx = __ldg(fb + sp);
            fy = __ldg(fb + HW + sp);
        }

        const float gx = (float)xp + fx;
        const float gy = (float)Y  + fy;
        const float x0f = floorf(gx), y0f = floorf(gy);
        const float wx = gx - x0f,    wy = gy - y0f;
        const int x0 = (int)x0f, y0 = (int)y0f;
        const int x1 = x0 + 1,   y1 = y0 + 1;

        const float vx0 = ((unsigned)x0 < WW) ? 1.f : 0.f;
        const float vx1 = ((unsigned)x1 < WW) ? 1.f : 0.f;
        const float vy0 = ((unsigned)y0 < HH) ? 1.f : 0.f;
        const float vy1 = ((unsigned)y1 < HH) ? 1.f : 0.f;

        const float w00 = (1.f - wx) * (1.f - wy) * vx0 * vy0;
        const float w01 = wx * (1.f - wy)         * vx1 * vy0;
        const float w10 = (1.f - wx) * wy         * vx0 * vy1;
        const float w11 = wx * wy                 * vx1 * vy1;

        const int cx0 = min(max(x0, 0), WW - 1);
        const int cx1 = min(max(x1, 0), WW - 1);
        const int cy0 = min(max(y0, 0), HH - 1);
        const int cy1 = min(max(y1, 0), HH - 1);

        const float4 t00 = __ldg((const float4*)(xTb + (size_t)(cy0 * WW + cx0) * CC) + ch4);
        const float4 t01 = __ldg((const float4*)(xTb + (size_t)(cy0 * WW + cx1) * CC) + ch4);
        const float4 t10 = __ldg((const float4*)(xTb + (size_t)(cy1 * WW + cx0) * CC) + ch4);
        const float4 t11 = __ldg((const float4*)(xTb + (size_t)(cy1 * WW + cx1) * CC) + ch4);

        float4 a;
        a.x = fmaf(w11, t11.x, fmaf(w10, t10.x, fmaf(w01, t01.x, w00 * t00.x)));
        a.y = fmaf(w11, t11.y, fmaf(w10, t10.y, fmaf(w01, t01.y, w00 * t00.y)));
        a.z = fmaf(w11, t11.z, fmaf(w10, t10.z, fmaf(w01, t01.z, w00 * t00.z)));
        a.w = fmaf(w11, t11.w, fmaf(w10, t10.w, fmaf(w01, t01.w, w00 * t00.w)));

        float* s = &st[g][pxl][ch4 * 4];
        s[0] = a.x; s[1] = a.y; s[2] = a.z; s[3] = a.w;
    }
    __syncthreads();

    // coalesced channel-major stores: rows r = g*64+c, lanes over 16 px
    float* ob = out + (size_t)b * 5 * CC * HW + (size_t)Y * WW + X0;
    const int px = l & 15;
    const int rsub = (w << 1) | (l >> 4);     // 0..15
    #pragma unroll
    for (int i = 0; i < 20; ++i) {
        const int r = i * 16 + rsub;          // 0..319
        const int g = r >> 6, c = r & 63;
        __stcs(ob + (size_t)r * HW + px, st[g][px][c]);
    }
}

extern "C" void kernel_launch(void* const* d_in, const int* in_sizes, int n_in,
                              void* d_out, int out_size) {
    const float* x    = (const float*)d_in[0];
    const float* flow = (const float*)d_in[1];
    float* out        = (float*)d_out;

    dim3 tgrid(HW / 32, CC / 32, BB);     // 2048 x 2 x 4
    dim3 tblk(32, 8);
    obmc_transpose<<<tgrid, tblk>>>(x);

    dim3 ggrid(WW / PXT, HH, BB);         // 16 x 256 x 4 = 16384 blocks
    obmc_gather<<<ggrid, 256>>>(flow, out);
}

// round 6
// speedup vs baseline: 1.4734x; 1.0514x over previous
#include <cuda_runtime.h>

// OBMC two-pass, channels-last + 5-group fusion.
// Pass 1: transpose x[B,C,H,W] -> xT[B,HW,C].
// Pass 2: one flow pixel -> all 5 group outputs (shared bilinear weights),
//         tap union = 12 float4 loads (vs 20 unfused). Warp = 2 pixels x
//         16 lanes (4 channels per lane). Outputs staged in smem, stored
//         as coalesced 16-px segments at shifted destinations.
// Borders: uncovered lines (g1 row255, g3 row0, g2 col255, g4 col0) are
// exact identity copies of x (OOB shift -> zero flow).

#define BB 4
#define CC 64
#define HH 256
#define WW 256
#define HW (HH * WW)
#define PXT 16

__device__ float g_xT[(size_t)BB * HW * CC];   // 67 MB scratch

// ---------------- Pass 1: transpose to channels-last ----------------
__global__ __launch_bounds__(256)
void obmc_transpose(const float* __restrict__ x) {
    __shared__ float t[32][33];
    const int b  = blockIdx.z;
    const int cb = blockIdx.y * 32;
    const int pb = blockIdx.x * 32;
    const int tx = threadIdx.x;
    const int ty = threadIdx.y;

    const float* xb = x + ((size_t)b * CC + cb) * HW + pb;
    #pragma unroll
    for (int i = 0; i < 32; i += 8)
        t[ty + i][tx] = xb[(size_t)(ty + i) * HW + tx];
    __syncthreads();

    float* o = g_xT + ((size_t)b * HW + pb) * CC + cb;
    #pragma unroll
    for (int i = 0; i < 32; i += 8)
        o[(size_t)(ty + i) * CC + tx] = t[tx][ty + i];
}

// ---------------- Pass 2: fused gather + store ----------------
__global__ __launch_bounds__(256, 3)
void obmc_gather(const float* __restrict__ flow, float* __restrict__ out) {
    __shared__ float st[5][PXT][65];   // stride 65: conflict-free read phase

    const int tid = threadIdx.x;
    const int l   = tid & 31;
    const int w   = tid >> 5;
    const int pxl = (w << 1) | (l >> 4);      // flow pixel 0..15 in block
    const int ch4 = l & 15;                   // 4-channel slice
    const int X0  = blockIdx.x * PXT;
    const int Y   = blockIdx.y;
    const int b   = blockIdx.z;
    const int xp  = X0 + pxl;
    const int pix = Y * WW + xp;

    const float* fb  = flow + (size_t)b * 2 * HW;
    const float* xTb = g_xT + (size_t)b * HW * CC;

    const float fx = __ldg(fb + pix);
    const float fy = __ldg(fb + HW + pix);

    const float gx = (float)xp + fx;
    const float gy = (float)Y  + fy;
    const float x0f = floorf(gx), y0f = floorf(gy);
    const float wx = gx - x0f,    wy = gy - y0f;
    const int x0 = (int)x0f, y0 = (int)y0f;

    // rows r0..r3 = y0-1..y0+2, cols c0..c3 = x0-1..x0+2 (clamped + validity)
    int rb_[4], cb_[4];
    float vr[4], vc[4];
    #pragma unroll
    for (int i = 0; i < 4; ++i) {
        const int r = y0 - 1 + i;
        vr[i] = ((unsigned)r < HH) ? 1.f : 0.f;
        rb_[i] = min(max(r, 0), HH - 1) * WW;
        const int c = x0 - 1 + i;
        vc[i] = ((unsigned)c < WW) ? 1.f : 0.f;
        cb_[i] = min(max(c, 0), WW - 1);
    }

    const float w00 = (1.f - wx) * (1.f - wy);
    const float w01 = wx * (1.f - wy);
    const float w10 = (1.f - wx) * wy;
    const float w11 = wx * wy;

    // 12 masked float4 taps
    #define TAP(nm, i, j) \
        float4 nm = __ldg((const float4*)(xTb + (size_t)(rb_[i] + cb_[j]) * CC) + ch4); \
        { const float m_ = vr[i] * vc[j]; nm.x *= m_; nm.y *= m_; nm.z *= m_; nm.w *= m_; }
    TAP(t10, 1, 0) TAP(t11, 1, 1) TAP(t12, 1, 2) TAP(t13, 1, 3)
    TAP(t20, 2, 0) TAP(t21, 2, 1) TAP(t22, 2, 2) TAP(t23, 2, 3)
    TAP(t01, 0, 1) TAP(t02, 0, 2) TAP(t31, 3, 1) TAP(t32, 3, 2)
    #undef TAP

    #define BLEND(dst, a, bq, cq, dq) \
        float4 dst; \
        dst.x = fmaf(w11, dq.x, fmaf(w10, cq.x, fmaf(w01, bq.x, w00 * a.x))); \
        dst.y = fmaf(w11, dq.y, fmaf(w10, cq.y, fmaf(w01, bq.y, w00 * a.y))); \
        dst.z = fmaf(w11, dq.z, fmaf(w10, cq.z, fmaf(w01, bq.z, w00 * a.z))); \
        dst.w = fmaf(w11, dq.w, fmaf(w10, cq.w, fmaf(w01, bq.w, w00 * a.w)));
    BLEND(v0, t11, t12, t21, t22)   // g0 @ (Y,   X)
    BLEND(v1, t01, t02, t11, t12)   // g1 @ (Y-1, X)
    BLEND(v3, t21, t22, t31, t32)   // g3 @ (Y+1, X)
    BLEND(v2, t10, t11, t20, t21)   // g2 @ (Y,   X-1)
    BLEND(v4, t12, t13, t22, t23)   // g4 @ (Y,   X+1)
    #undef BLEND

    {
        float* s;
        s = &st[0][pxl][ch4 * 4]; s[0]=v0.x; s[1]=v0.y; s[2]=v0.z; s[3]=v0.w;
        s = &st[1][pxl][ch4 * 4]; s[0]=v1.x; s[1]=v1.y; s[2]=v1.z; s[3]=v1.w;
        s = &st[2][pxl][ch4 * 4]; s[0]=v2.x; s[1]=v2.y; s[2]=v2.z; s[3]=v2.w;
        s = &st[3][pxl][ch4 * 4]; s[0]=v3.x; s[1]=v3.y; s[2]=v3.z; s[3]=v3.w;
        s = &st[4][pxl][ch4 * 4]; s[0]=v4.x; s[1]=v4.y; s[2]=v4.z; s[3]=v4.w;
    }

    // rare border identity copies (exact): center value = x at (Y,xp)
    if ((Y == 0) | (Y == HH - 1) | (xp == 0) | (xp == WW - 1)) {
        const float4 cv = __ldg((const float4*)(xTb + (size_t)pix * CC) + ch4);
        const float cvv[4] = {cv.x, cv.y, cv.z, cv.w};
        #pragma unroll
        for (int k = 0; k < 4; ++k) {
            const int c = ch4 * 4 + k;
            const size_t base = ((size_t)(b * 5) * CC + c) * HW + pix;
            if (Y == HH - 1)  __stcs(out + base + (size_t)1 * CC * HW, cvv[k]);
            if (Y == 0)       __stcs(out + base + (size_t)3 * CC * HW, cvv[k]);
            if (xp == WW - 1) __stcs(out + base + (size_t)2 * CC * HW, cvv[k]);
            if (xp == 0)      __stcs(out + base + (size_t)4 * CC * HW, cvv[k]);
        }
    }
    __syncthreads();

    // coalesced stores at shifted destinations
    const int px   = tid & 15;
    const int rsub = tid >> 4;                 // 0..15
    float* ob = out + (size_t)(b * 5) * CC * HW + (size_t)Y * WW + X0;
    #pragma unroll
    for (int i = 0; i < 20; ++i) {
        const int r = i * 16 + rsub;           // 0..319 (g*64 + c)
        const int g = r >> 6;
        const float v = st[g][px][r & 63];
        float* p = ob + (size_t)r * HW + px;
        bool ok = true;
        if (g == 1) { p -= WW; ok = (Y >= 1); }
        else if (g == 3) { p += WW; ok = (Y <= HH - 2); }
        else if (g == 2) { p -= 1;  ok = (X0 + px >= 1); }
        else if (g == 4) { p += 1;  ok = (X0 + px <= WW - 2); }
        if (ok) __stcs(p, v);
    }
}

extern "C" void kernel_launch(void* const* d_in, const int* in_sizes, int n_in,
                              void* d_out, int out_size) {
    const float* x    = (const float*)d_in[0];
    const float* flow = (const float*)d_in[1];
    float* out        = (float*)d_out;

    dim3 tgrid(HW / 32, CC / 32, BB);
    dim3 tblk(32, 8);
    obmc_transpose<<<tgrid, tblk>>>(x);

    dim3 ggrid(WW / PXT, HH, BB);   // 16 x 256 x 4
    obmc_gather<<<ggrid, 256>>>(flow, out);
}